// round 16
// baseline (speedup 1.0000x reference)
#include <cuda_runtime.h>
#include <cuda_fp16.h>
#include <math.h>
#include <stdint.h>

// ---------------- problem constants ----------------
#define BB   16
#define SS   256
#define NVV  196
#define DD   768
#define FFD  2048
#define VOC  30522
#define NL   6
#define NHH  8
#define HDIM 96
#define MQ   (BB*SS)          // 4096
#define MKV  (BB*NVV)         // 3136
#define BHH  (BB*NHH)         // 128
#define MDEC (BB*(SS-1))      // 4080
#define KVSZ (BHH*NVV*HDIM)

// ---------------- scratch (static device memory; no allocations) ----------------
__device__ float  g_x  [MQ*DD];
__device__ __half g_xh [MQ*DD];
__device__ __half g_qh [BHH*SS*HDIM];
__device__ __half g_kh [BHH*SS*HDIM];
__device__ __half g_vh [BHH*SS*HDIM];
__device__ __half g_kh6[NL*KVSZ];
__device__ __half g_vh6[NL*KVSZ];
__device__ __half g_att[MQ*DD];
__device__ __half g_yh [MQ*DD];
__device__ __half g_ff [MQ*FFD];
__device__ __half g_dech[MDEC*DD];
__device__ __half g_fvh[MKV*DD];

__device__ __half g_w_selfin [NL*3*DD*DD];
__device__ __half g_w_selfout[NL*DD*DD];
__device__ __half g_w_cq     [NL*DD*DD];
__device__ __half g_w_ckv    [NL*2*DD*DD];
__device__ __half g_w_crossout[NL*DD*DD];
__device__ __half g_w_lin1   [NL*FFD*DD];
__device__ __half g_w_lin2   [NL*DD*FFD];
__device__ __half g_w_fc     [VOC*DD];
__device__ float  g_b_ckv    [NL*2*DD];

// ---------------- reductions ----------------
__device__ __forceinline__ float blk_sum256(float v) {
    __shared__ float sh[8];
    #pragma unroll
    for (int o = 16; o > 0; o >>= 1) v += __shfl_xor_sync(0xffffffffu, v, o);
    __syncthreads();
    if ((threadIdx.x & 31) == 0) sh[threadIdx.x >> 5] = v;
    __syncthreads();
    float r = sh[0];
    #pragma unroll
    for (int i = 1; i < 8; i++) r += sh[i];
    return r;
}

__device__ __forceinline__ float blk_max256(float v) {
    __shared__ float sh[8];
    #pragma unroll
    for (int o = 16; o > 0; o >>= 1) v = fmaxf(v, __shfl_xor_sync(0xffffffffu, v, o));
    __syncthreads();
    if ((threadIdx.x & 31) == 0) sh[threadIdx.x >> 5] = v;
    __syncthreads();
    float r = sh[0];
    #pragma unroll
    for (int i = 1; i < 8; i++) r = fmaxf(r, sh[i]);
    return r;
}

// ---------------- mma helpers ----------------
__device__ __forceinline__ void mma_f16(float (&d)[4], const unsigned (&a)[4], const unsigned (&b)[2]) {
    asm volatile(
        "mma.sync.aligned.m16n8k16.row.col.f32.f16.f16.f32 "
        "{%0,%1,%2,%3}, {%4,%5,%6,%7}, {%8,%9}, {%0,%1,%2,%3};\n"
        : "+f"(d[0]), "+f"(d[1]), "+f"(d[2]), "+f"(d[3])
        : "r"(a[0]), "r"(a[1]), "r"(a[2]), "r"(a[3]), "r"(b[0]), "r"(b[1]));
}

__device__ __forceinline__ void ldsm4(unsigned &d0, unsigned &d1, unsigned &d2, unsigned &d3, uint32_t a) {
    asm volatile("ldmatrix.sync.aligned.m8n8.x4.shared.b16 {%0,%1,%2,%3}, [%4];"
                 : "=r"(d0), "=r"(d1), "=r"(d2), "=r"(d3) : "r"(a));
}

__device__ __forceinline__ uint32_t smem_u32(const void* p) {
    uint32_t a;
    asm("{ .reg .u64 t; cvta.to.shared.u64 t, %1; cvt.u32.u64 %0, t; }" : "=r"(a) : "l"(p));
    return a;
}

__device__ __forceinline__ void cp16(uint32_t dst, const void* src, bool pred) {
    int sz = pred ? 16 : 0;
    asm volatile("cp.async.cg.shared.global [%0], [%1], 16, %2;" :: "r"(dst), "l"(src), "r"(sz));
}
#define CP_COMMIT() asm volatile("cp.async.commit_group;" ::: "memory")
#define CP_WAIT1()  asm volatile("cp.async.wait_group 1;" ::: "memory")

// ---------------- fp32 -> fp16 conversion passes ----------------
#define NSEG 7
struct CvtSegs {
    const float4* src[NSEG];
    uint2*        dst[NSEG];
    int           n4[NSEG];
};

__global__ void cvt_mega_kernel(CvtSegs segs) {
    int tid0 = blockIdx.x*blockDim.x + threadIdx.x;
    int stride = gridDim.x*blockDim.x;
    #pragma unroll
    for (int s = 0; s < NSEG; s++) {
        const float4* in = segs.src[s];
        uint2* out = segs.dst[s];
        int n4 = segs.n4[s];
        for (int i = tid0; i < n4; i += stride) {
            float4 v = in[i];
            __half2 h0 = __floats2half2_rn(v.x, v.y);
            __half2 h1 = __floats2half2_rn(v.z, v.w);
            out[i] = make_uint2(*(uint32_t*)&h0, *(uint32_t*)&h1);
        }
    }
}

// fused: split cross_in_w [L,3*DD,DD] into per-layer Q [L,DD,DD] and KV [L,2*DD,DD], fp16
__global__ void cvt_split_crossin_kernel(const float4* __restrict__ in,
                                         uint2* __restrict__ wcq, uint2* __restrict__ wckv) {
    const int PR = DD/4;
    const int n4 = NL*3*DD*PR;
    int i = blockIdx.x*blockDim.x + threadIdx.x;
    int stride = gridDim.x*blockDim.x;
    for (; i < n4; i += stride) {
        float4 v = in[i];
        __half2 h0 = __floats2half2_rn(v.x, v.y);
        __half2 h1 = __floats2half2_rn(v.z, v.w);
        uint2 hv = make_uint2(*(uint32_t*)&h0, *(uint32_t*)&h1);
        int row = i / PR, col = i - row*PR;
        int l = row / (3*DD), r = row - l*3*DD;
        if (r < DD) wcq [(size_t)l*DD*PR   + (size_t)r*PR        + col] = hv;
        else        wckv[(size_t)l*2*DD*PR + (size_t)(r - DD)*PR + col] = hv;
    }
}

__global__ void gather_ckv_bias_kernel(const float* __restrict__ cib) {
    int i = blockIdx.x*blockDim.x + threadIdx.x;
    if (i >= NL*2*DD) return;
    int l = i / (2*DD);
    int rem = i - l*2*DD;
    g_b_ckv[i] = cib[l*3*DD + DD + rem];
}

// ---------------- main dense GEMM (fp16 mma m16n8k16, cp.async 3-stage, 128x128, K-chunk 64) ----------------
#define SKH2 72                         // row stride in halves (144 B; r*144 mod 128 = r*16, conflict-free)
#define STG_B (128*SKH2*2*2)            // bytes per stage (A+B) = 36864
#define GEMM_DSMEM (3*STG_B)            // 110592

__global__ __launch_bounds__(256, 2) void gemm_nt_f16(
    const __half* __restrict__ A, const __half* __restrict__ Bm,
    const float* __restrict__ bias, float* __restrict__ C, __half* __restrict__ Ch,
    int M, int N, int K, int relu, int mode,
    __half* __restrict__ dq, __half* __restrict__ dk, __half* __restrict__ dv)
{
    extern __shared__ unsigned sm[];
    const uint32_t sb = smem_u32(sm);
    const int tid  = threadIdx.x;
    const int lane = tid & 31;
    const int wid  = tid >> 5;
    const int m0   = blockIdx.y * 128;
    const int n0   = blockIdx.x * 128;
    const int wm   = (wid & 3) * 32;
    const int wn   = (wid >> 2) * 64;
    const int g    = lane >> 2;
    const int t    = lane & 3;

    const uint32_t aoffB = (uint32_t)((((lane & 7) + ((lane >> 3) & 1)*8)*SKH2 + ((lane >> 4) & 1)*8) * 2);
    const uint32_t boffB = (uint32_t)((((lane & 7) + ((lane >> 4) & 1)*8)*SKH2 + ((lane >> 3) & 1)*8) * 2);

    const int lrow = tid >> 1;          // 0..127
    const int segb = (tid & 1) * 4;     // 0 or 4 (of 8 16B segs per 64-half row)

    float acc[2][8][4];
    #pragma unroll
    for (int mi = 0; mi < 2; mi++)
        #pragma unroll
        for (int ni = 0; ni < 8; ni++)
            #pragma unroll
            for (int e = 0; e < 4; e++) acc[mi][ni][e] = 0.f;

    const int NC = K >> 6;              // K % 64 == 0, NC >= 2

    #pragma unroll
    for (int pc = 0; pc < 2; pc++) {
        const int k0 = pc << 6;
        const uint32_t sA = sb + (uint32_t)(pc * STG_B);
        const uint32_t sB = sA + (uint32_t)(128*SKH2*2);
        #pragma unroll
        for (int e = 0; e < 4; e++) {
            int seg = segb + e;
            int gm = m0 + lrow;
            cp16(sA + (uint32_t)(lrow*SKH2*2 + seg*16),
                 A + (size_t)(gm < M ? gm : 0)*K + k0 + seg*8, gm < M);
            int gn = n0 + lrow;
            cp16(sB + (uint32_t)(lrow*SKH2*2 + seg*16),
                 Bm + (size_t)(gn < N ? gn : 0)*K + k0 + seg*8, gn < N);
        }
        CP_COMMIT();
    }

    for (int c = 0; c < NC; c++) {
        CP_WAIT1();
        __syncthreads();

        if (c + 2 < NC) {
            const int k0 = (c + 2) << 6;
            const int s = (c + 2) % 3;
            const uint32_t sA = sb + (uint32_t)(s * STG_B);
            const uint32_t sB = sA + (uint32_t)(128*SKH2*2);
            #pragma unroll
            for (int e = 0; e < 4; e++) {
                int seg = segb + e;
                int gm = m0 + lrow;
                cp16(sA + (uint32_t)(lrow*SKH2*2 + seg*16),
                     A + (size_t)(gm < M ? gm : 0)*K + k0 + seg*8, gm < M);
                int gn = n0 + lrow;
                cp16(sB + (uint32_t)(lrow*SKH2*2 + seg*16),
                     Bm + (size_t)(gn < N ? gn : 0)*K + k0 + seg*8, gn < N);
            }
        }
        CP_COMMIT();

        const int s = c % 3;
        const uint32_t Acur = sb + (uint32_t)(s * STG_B);
        const uint32_t Bcur = Acur + (uint32_t)(128*SKH2*2);
        #pragma unroll
        for (int ks = 0; ks < 4; ks++) {
            unsigned a[2][4], b[8][2];
            #pragma unroll
            for (int mi = 0; mi < 2; mi++)
                ldsm4(a[mi][0], a[mi][1], a[mi][2], a[mi][3],
                      Acur + (uint32_t)(((wm + mi*16)*SKH2 + ks*16)*2) + aoffB);
            #pragma unroll
            for (int nj = 0; nj < 4; nj++)
                ldsm4(b[2*nj][0], b[2*nj][1], b[2*nj+1][0], b[2*nj+1][1],
                      Bcur + (uint32_t)(((wn + nj*16)*SKH2 + ks*16)*2) + boffB);
            #pragma unroll
            for (int mi = 0; mi < 2; mi++)
                #pragma unroll
                for (int ni = 0; ni < 8; ni++)
                    mma_f16(acc[mi][ni], a[mi], b[ni]);
        }
    }

    // ---- epilogue ----
    #pragma unroll
    for (int mi = 0; mi < 2; mi++) {
        #pragma unroll
        for (int half_ = 0; half_ < 2; half_++) {
            int r = m0 + wm + mi*16 + g + half_*8;
            if (r >= M) continue;
            #pragma unroll
            for (int ni = 0; ni < 8; ni++) {
                int cn = n0 + wn + ni*8 + 2*t;
                if (cn >= N) continue;
                float v0 = acc[mi][ni][half_*2 + 0];
                float v1 = acc[mi][ni][half_*2 + 1];
                if (bias) { v0 += bias[cn]; if (cn+1 < N) v1 += bias[cn+1]; }
                if (mode == 0) {
                    if (relu) { v0 = fmaxf(v0, 0.f); v1 = fmaxf(v1, 0.f); }
                    if (Ch) {
                        __half2 hv = __floats2half2_rn(v0, v1);
                        if (cn + 1 < N) *(__half2*)(Ch + (size_t)r*N + cn) = hv;
                        else            Ch[(size_t)r*N + cn] = __float2half(v0);
                    } else {
                        if (cn + 1 < N) *(float2*)(C + (size_t)r*N + cn) = make_float2(v0, v1);
                        else            C[(size_t)r*N + cn] = v0;
                    }
                } else {
                    int bb_, s_, which, rem, hh, dd;
                    __half* base;
                    if (mode == 1) {         // self QKV
                        bb_ = r >> 8; s_ = r & 255;
                        which = cn / DD; rem = cn - which*DD;
                        hh = rem / HDIM; dd = rem - hh*HDIM;
                        base = (which == 0) ? dq : (which == 1) ? dk : dv;
                        base += (((size_t)((bb_<<3) + hh))*SS + s_)*HDIM + dd;
                    } else {                 // mode 3: batched cross KV
                        bb_ = r / NVV; s_ = r - bb_*NVV;
                        int l = cn / (2*DD);
                        rem = cn - l*2*DD;
                        which = rem / DD;
                        int rem2 = rem - which*DD;
                        hh = rem2 / HDIM; dd = rem2 - hh*HDIM;
                        base = ((which == 0) ? dk : dv) + (size_t)l*KVSZ;
                        base += (((size_t)((bb_<<3) + hh))*NVV + s_)*HDIM + dd;
                    }
                    *(__half2*)base = __floats2half2_rn(v0, v1);
                }
            }
        }
    }
}

// ---------------- small-N GEMM (128x64 tile, K-chunk 32) ----------------
#define SKH 40
#define STG64_B ((128+64)*SKH*2)
#define GEMM64_DSMEM (3*STG64_B)

__global__ __launch_bounds__(256, 2) void gemm_nt_f16_n64(
    const __half* __restrict__ A, const __half* __restrict__ Bm,
    const float* __restrict__ bias, __half* __restrict__ Ch,
    int M, int N, int K, int mode, __half* __restrict__ dq)
{
    extern __shared__ unsigned sm[];
    const uint32_t sb = smem_u32(sm);
    const int tid  = threadIdx.x;
    const int lane = tid & 31;
    const int wid  = tid >> 5;
    const int m0   = blockIdx.y * 128;
    const int n0   = blockIdx.x * 64;
    const int wm   = (wid & 3) * 32;
    const int wn   = (wid >> 2) * 32;
    const int g    = lane >> 2;
    const int t    = lane & 3;

    const uint32_t aoffB = (uint32_t)((((lane & 7) + ((lane >> 3) & 1)*8)*SKH + ((lane >> 4) & 1)*8) * 2);
    const uint32_t boffB = (uint32_t)((((lane & 7) + ((lane >> 4) & 1)*8)*SKH + ((lane >> 3) & 1)*8) * 2);

    const int larow = tid >> 1;
    const int lasegb = (tid & 1) * 2;
    const int lbrow = tid >> 2;
    const int lbseg = tid & 3;

    float acc[2][4][4];
    #pragma unroll
    for (int mi = 0; mi < 2; mi++)
        #pragma unroll
        for (int ni = 0; ni < 4; ni++)
            #pragma unroll
            for (int e = 0; e < 4; e++) acc[mi][ni][e] = 0.f;

    const int NC = K >> 5;

    #pragma unroll
    for (int pc = 0; pc < 2; pc++) {
        const int k0 = pc << 5;
        const uint32_t sA = sb + (uint32_t)(pc * STG64_B);
        const uint32_t sB = sA + (uint32_t)(128*SKH*2);
        #pragma unroll
        for (int e = 0; e < 2; e++) {
            int seg = lasegb + e;
            int gm = m0 + larow;
            cp16(sA + (uint32_t)(larow*SKH*2 + seg*16),
                 A + (size_t)(gm < M ? gm : 0)*K + k0 + seg*8, gm < M);
        }
        {
            int gn = n0 + lbrow;
            cp16(sB + (uint32_t)(lbrow*SKH*2 + lbseg*16),
                 Bm + (size_t)(gn < N ? gn : 0)*K + k0 + lbseg*8, gn < N);
        }
        CP_COMMIT();
    }

    for (int c = 0; c < NC; c++) {
        CP_WAIT1();
        __syncthreads();

        if (c + 2 < NC) {
            const int k0 = (c + 2) << 5;
            const int s = (c + 2) % 3;
            const uint32_t sA = sb + (uint32_t)(s * STG64_B);
            const uint32_t sB = sA + (uint32_t)(128*SKH*2);
            #pragma unroll
            for (int e = 0; e < 2; e++) {
                int seg = lasegb + e;
                int gm = m0 + larow;
                cp16(sA + (uint32_t)(larow*SKH*2 + seg*16),
                     A + (size_t)(gm < M ? gm : 0)*K + k0 + seg*8, gm < M);
            }
            {
                int gn = n0 + lbrow;
                cp16(sB + (uint32_t)(lbrow*SKH*2 + lbseg*16),
                     Bm + (size_t)(gn < N ? gn : 0)*K + k0 + lbseg*8, gn < N);
            }
        }
        CP_COMMIT();

        const int s = c % 3;
        const uint32_t Acur = sb + (uint32_t)(s * STG64_B);
        const uint32_t Bcur = Acur + (uint32_t)(128*SKH*2);
        #pragma unroll
        for (int ks = 0; ks < 2; ks++) {
            unsigned a[2][4], b[4][2];
            #pragma unroll
            for (int mi = 0; mi < 2; mi++)
                ldsm4(a[mi][0], a[mi][1], a[mi][2], a[mi][3],
                      Acur + (uint32_t)(((wm + mi*16)*SKH + ks*16)*2) + aoffB);
            #pragma unroll
            for (int nj = 0; nj < 2; nj++)
                ldsm4(b[2*nj][0], b[2*nj][1], b[2*nj+1][0], b[2*nj+1][1],
                      Bcur + (uint32_t)(((wn + nj*16)*SKH + ks*16)*2) + boffB);
            #pragma unroll
            for (int mi = 0; mi < 2; mi++)
                #pragma unroll
                for (int ni = 0; ni < 4; ni++)
                    mma_f16(acc[mi][ni], a[mi], b[ni]);
        }
    }

    #pragma unroll
    for (int mi = 0; mi < 2; mi++) {
        #pragma unroll
        for (int half_ = 0; half_ < 2; half_++) {
            int r = m0 + wm + mi*16 + g + half_*8;
            if (r >= M) continue;
            #pragma unroll
            for (int ni = 0; ni < 4; ni++) {
                int cn = n0 + wn + ni*8 + 2*t;
                if (cn >= N) continue;
                float v0 = acc[mi][ni][half_*2 + 0];
                float v1 = acc[mi][ni][half_*2 + 1];
                if (bias) { v0 += bias[cn]; if (cn+1 < N) v1 += bias[cn+1]; }
                if (mode == 0) {
                    __half2 hv = __floats2half2_rn(v0, v1);
                    if (cn + 1 < N) *(__half2*)(Ch + (size_t)r*N + cn) = hv;
                    else            Ch[(size_t)r*N + cn] = __float2half(v0);
                } else {
                    int bb_ = r >> 8, s_ = r & 255;
                    int hh = cn / HDIM, dd = cn - hh*HDIM;
                    __half* base = dq + (((size_t)((bb_<<3) + hh))*SS + s_)*HDIM + dd;
                    *(__half2*)base = __floats2half2_rn(v0, v1);
                }
            }
        }
    }
}

// ---------------- fused flash attention (fp16 mma m16n8k16) ----------------
#define FKS 104
#define FVS 40

__global__ __launch_bounds__(256) void flash_attn(
    const __half* __restrict__ Qh, const __half* __restrict__ Kh, const __half* __restrict__ Vh,
    __half* __restrict__ Oatt, int kvlen, int causal)
{
    __shared__ __half Ks[32*FKS];
    __shared__ __half Vs[96*FVS];
    __shared__ __half Ps[8][16*FVS];
    const int tid = threadIdx.x, w = tid >> 5, lane = tid & 31;
    const int g = lane >> 2, t = lane & 3;
    const int z = blockIdx.y;
    const int b = z >> 3, h = z & 7;
    const int q0 = blockIdx.x * 128;
    const float scale = 0.1020620726159658f;

    const __half* Qb = Qh + ((size_t)z*SS + q0)*HDIM;
    const __half* Kb = Kh + (size_t)z*kvlen*HDIM;
    const __half* Vb = Vh + (size_t)z*kvlen*HDIM;

    unsigned qa[6][4];
    {
        const __half* qr0 = Qb + (w*16 + g)*HDIM;
        const __half* qr1 = qr0 + 8*HDIM;
        #pragma unroll
        for (int ks = 0; ks < 6; ks++) {
            qa[ks][0] = *(const uint32_t*)(qr0 + ks*16 + 2*t);
            qa[ks][1] = *(const uint32_t*)(qr1 + ks*16 + 2*t);
            qa[ks][2] = *(const uint32_t*)(qr0 + ks*16 + 2*t + 8);
            qa[ks][3] = *(const uint32_t*)(qr1 + ks*16 + 2*t + 8);
        }
    }

    float oacc[12][4];
    #pragma unroll
    for (int n = 0; n < 12; n++) { oacc[n][0]=0.f; oacc[n][1]=0.f; oacc[n][2]=0.f; oacc[n][3]=0.f; }
    float m0 = -1e30f, m1 = -1e30f, l0 = 0.f, l1 = 0.f;
    const int row0 = q0 + w*16 + g;
    const int row1 = row0 + 8;

    const uint32_t KsA = smem_u32(Ks);
    const uint32_t VsA = smem_u32(Vs);
    const uint32_t PsA = smem_u32(Ps[w]);
    const uint32_t boffK = (uint32_t)((((lane & 7) + ((lane >> 4) & 1)*8)*FKS + ((lane >> 3) & 1)*8) * 2);
    const uint32_t boffV = (uint32_t)((((lane & 7) + ((lane >> 4) & 1)*8)*FVS + ((lane >> 3) & 1)*8) * 2);
    const uint32_t aoffP = (uint32_t)((((lane & 7) + ((lane >> 3) & 1)*8)*FVS + ((lane >> 4) & 1)*8) * 2);

    int ntiles = (kvlen + 31) >> 5;
    if (causal) { int lim = ((q0 + 127) >> 5) + 1; if (lim < ntiles) ntiles = lim; }

    for (int j = 0; j < ntiles; j++) {
        const int k0 = j*32;

        #pragma unroll
        for (int it = 0; it < 2; it++) {
            int idx = it*256 + tid;
            if (idx < 384) {
                int key = idx / 12, q8 = idx - key*12;
                uint4 v = make_uint4(0u,0u,0u,0u);
                if (k0 + key < kvlen) v = *(const uint4*)(Kb + (size_t)(k0+key)*HDIM + q8*8);
                *(uint4*)(Ks + key*FKS + q8*8) = v;
            }
        }
        #pragma unroll
        for (int it = 0; it < 3; it++) {
            int idx = it*256 + tid;
            int key = idx & 31, dq4 = idx >> 5;
            uint2 v = make_uint2(0u,0u);
            if (k0 + key < kvlen) v = *(const uint2*)(Vb + (size_t)(k0+key)*HDIM + dq4*4);
            __half2 p0 = *(__half2*)&v.x;
            __half2 p1 = *(__half2*)&v.y;
            Vs[(dq4*4+0)*FVS + key] = __low2half(p0);
            Vs[(dq4*4+1)*FVS + key] = __high2half(p0);
            Vs[(dq4*4+2)*FVS + key] = __low2half(p1);
            Vs[(dq4*4+3)*FVS + key] = __high2half(p1);
        }
        __syncthreads();

        const bool active = !(causal && k0 > q0 + w*16 + 15);
        if (active) {
            float sacc[4][4];
            #pragma unroll
            for (int n = 0; n < 4; n++) { sacc[n][0]=0.f; sacc[n][1]=0.f; sacc[n][2]=0.f; sacc[n][3]=0.f; }
            #pragma unroll
            for (int ks = 0; ks < 6; ks++) {
                unsigned bb[4][2];
                ldsm4(bb[0][0], bb[0][1], bb[1][0], bb[1][1],
                      KsA + (uint32_t)(ks*16*2) + boffK);
                ldsm4(bb[2][0], bb[2][1], bb[3][0], bb[3][1],
                      KsA + (uint32_t)((16*FKS + ks*16)*2) + boffK);
                #pragma unroll
                for (int n = 0; n < 4; n++) mma_f16(sacc[n], qa[ks], bb[n]);
            }
            #pragma unroll
            for (int n = 0; n < 4; n++) {
                sacc[n][0] *= scale; sacc[n][1] *= scale;
                sacc[n][2] *= scale; sacc[n][3] *= scale;
            }

            const bool need_mask = causal || (k0 + 31 >= kvlen);
            if (need_mask) {
                #pragma unroll
                for (int n = 0; n < 4; n++) {
                    int colb = k0 + n*8 + 2*t;
                    #pragma unroll
                    for (int e = 0; e < 4; e++) {
                        int col = colb + (e & 1);
                        int row = (e < 2) ? row0 : row1;
                        if (col >= kvlen || (causal && col > row)) sacc[n][e] = -1e9f;
                    }
                }
            }

            float tm0 = fmaxf(fmaxf(sacc[0][0], sacc[0][1]), fmaxf(sacc[1][0], sacc[1][1]));
            tm0 = fmaxf(tm0, fmaxf(fmaxf(sacc[2][0], sacc[2][1]), fmaxf(sacc[3][0], sacc[3][1])));
            float tm1 = fmaxf(fmaxf(sacc[0][2], sacc[0][3]), fmaxf(sacc[1][2], sacc[1][3]));
            tm1 = fmaxf(tm1, fmaxf(fmaxf(sacc[2][2], sacc[2][3]), fmaxf(sacc[3][2], sacc[3][3])));
            tm0 = fmaxf(tm0, __shfl_xor_sync(0xffffffffu, tm0, 1));
            tm0 = fmaxf(tm0, __shfl_xor_sync(0xffffffffu, tm0, 2));
            tm1 = fmaxf(tm1, __shfl_xor_sync(0xffffffffu, tm1, 1));
            tm1 = fmaxf(tm1, __shfl_xor_sync(0xffffffffu, tm1, 2));
            float mn0 = fmaxf(m0, tm0), mn1 = fmaxf(m1, tm1);
            float a0 = __expf(m0 - mn0), a1 = __expf(m1 - mn1);
            float rs0 = 0.f, rs1 = 0.f;
            #pragma unroll
            for (int n = 0; n < 4; n++) {
                sacc[n][0] = __expf(sacc[n][0] - mn0); rs0 += sacc[n][0];
                sacc[n][1] = __expf(sacc[n][1] - mn0); rs0 += sacc[n][1];
                sacc[n][2] = __expf(sacc[n][2] - mn1); rs1 += sacc[n][2];
                sacc[n][3] = __expf(sacc[n][3] - mn1); rs1 += sacc[n][3];
            }
            rs0 += __shfl_xor_sync(0xffffffffu, rs0, 1);
            rs0 += __shfl_xor_sync(0xffffffffu, rs0, 2);
            rs1 += __shfl_xor_sync(0xffffffffu, rs1, 1);
            rs1 += __shfl_xor_sync(0xffffffffu, rs1, 2);
            l0 = l0*a0 + rs0; l1 = l1*a1 + rs1;
            m0 = mn0; m1 = mn1;
            #pragma unroll
            for (int n = 0; n < 12; n++) {
                oacc[n][0] *= a0; oacc[n][1] *= a0;
                oacc[n][2] *= a1; oacc[n][3] *= a1;
            }

            #pragma unroll
            for (int n = 0; n < 4; n++) {
                *(__half2*)((char*)Ps[w] + ((g    )*FVS + n*8 + 2*t)*2) = __floats2half2_rn(sacc[n][0], sacc[n][1]);
                *(__half2*)((char*)Ps[w] + ((g + 8)*FVS + n*8 + 2*t)*2) = __floats2half2_rn(sacc[n][2], sacc[n][3]);
            }
            __syncwarp();

            #pragma unroll
            for (int ks = 0; ks < 2; ks++) {
                unsigned pa[4];
                ldsm4(pa[0], pa[1], pa[2], pa[3], PsA + (uint32_t)(ks*16*2) + aoffP);
                unsigned vb[12][2];
                #pragma unroll
                for (int nj = 0; nj < 6; nj++)
                    ldsm4(vb[2*nj][0], vb[2*nj][1], vb[2*nj+1][0], vb[2*nj+1][1],
                          VsA + (uint32_t)((nj*16*FVS + ks*16)*2) + boffV);
                #pragma unroll
                for (int n = 0; n < 12; n++) mma_f16(oacc[n], pa, vb[n]);
            }
        }
        __syncthreads();
    }

    float inv0 = 1.f / l0, inv1 = 1.f / l1;
    __half* o0 = Oatt + ((size_t)(b*SS + row0))*DD + h*HDIM;
    __half* o1 = o0 + (size_t)8*DD;
    #pragma unroll
    for (int n = 0; n < 12; n++) {
        int cc = n*8 + 2*t;
        *(__half2*)(o0 + cc) = __floats2half2_rn(oacc[n][0]*inv0, oacc[n][1]*inv0);
        *(__half2*)(o1 + cc) = __floats2half2_rn(oacc[n][2]*inv1, oacc[n][3]*inv1);
    }
}

// ---------------- elementwise / softmax / LN ----------------
__global__ void add_pe_kernel(const float* __restrict__ te) {
    int idx = blockIdx.x*blockDim.x + threadIdx.x;
    if (idx >= MQ*DD) return;
    int d = idx % DD;
    int s = (idx / DD) % SS;
    int i2 = d & ~1;
    const float kfac = 9.210340371976184f / (float)DD;
    float div = expf(-(float)i2 * kfac);
    float ang = (float)s * div;
    float pe = (d & 1) ? cosf(ang) : sinf(ang);
    float v = te[idx] + pe;
    g_x[idx] = v;
    g_xh[idx] = __float2half(v);
}

__global__ __launch_bounds__(256) void add_ln_kernel(const __half* __restrict__ y,
                                                     const float* __restrict__ w,
                                                     const float* __restrict__ b) {
    int r = blockIdx.x;
    int t = threadIdx.x;
    float vs[3];
    float s = 0.f;
    #pragma unroll
    for (int i = 0; i < 3; i++) {
        int c = t + i*256;
        vs[i] = g_x[(size_t)r*DD + c] + __half2float(y[(size_t)r*DD + c]);
        s += vs[i];
    }
    float mean = blk_sum256(s) * (1.f/DD);
    float ss = 0.f;
    #pragma unroll
    for (int i = 0; i < 3; i++) { float d0 = vs[i] - mean; ss += d0*d0; }
    float var = blk_sum256(ss) * (1.f/DD);
    float inv = rsqrtf(var + 1e-5f);
    #pragma unroll
    for (int i = 0; i < 3; i++) {
        int c = t + i*256;
        float o = (vs[i] - mean)*inv*w[c] + b[c];
        g_x[(size_t)r*DD + c] = o;
        g_xh[(size_t)r*DD + c] = __float2half(o);
    }
}

__global__ __launch_bounds__(256) void dec_softmax_kernel(float* __restrict__ outF) {
    int r = blockIdx.x;
    int t = threadIdx.x;
    int b = r / (SS-1);
    int s = r - b*(SS-1);
    const float* p = g_x + ((size_t)(b*SS + s))*DD;
    float vs[3]; float m = -3.0e38f;
    #pragma unroll
    for (int i = 0; i < 3; i++) { vs[i] = p[t + i*256]; m = fmaxf(m, vs[i]); }
    float mx = blk_max256(m);
    float s0 = 0.f;
    float ex[3];
    #pragma unroll
    for (int i = 0; i < 3; i++) { ex[i] = expf(vs[i] - mx); s0 += ex[i]; }
    float sum = blk_sum256(s0);
    #pragma unroll
    for (int i = 0; i < 3; i++) {
        int c = t + i*256;
        outF[(size_t)r*DD + c] = ex[i] / sum;
        g_dech[(size_t)r*DD + c] = __float2half(vs[i]);
    }
}

// ---------------- host orchestration ----------------
static inline dim3 gemm_grid(int M, int N) { return dim3((N + 127)/128, (M + 127)/128); }
static inline dim3 gemm64_grid(int M, int N) { return dim3((N + 63)/64, (M + 127)/128); }

extern "C" void kernel_launch(void* const* d_in, const int* in_sizes, int n_in,
                              void* d_out, int out_size) {
    (void)in_sizes; (void)n_in; (void)out_size;
    const float* fv          = (const float*)d_in[0];
    const float* te          = (const float*)d_in[1];
    const float* self_in_w   = (const float*)d_in[2];
    const float* self_in_b   = (const float*)d_in[3];
    const float* self_out_w  = (const float*)d_in[4];
    const float* self_out_b  = (const float*)d_in[5];
    const float* cross_in_w  = (const float*)d_in[6];
    const float* cross_in_b  = (const float*)d_in[7];
    const float* cross_out_w = (const float*)d_in[8];
    const float* cross_out_b = (const float*)d_in[9];
    const float* lin1_w      = (const float*)d_in[10];
    const float* lin1_b      = (const float*)d_in[11];
    const float* lin2_w      = (const float*)d_in[12];
    const float* lin2_b      = (const float*)d_in[13];
    const float* ln_w        = (const float*)d_in[14];
    const float* ln_b        = (const float*)d_in[15];
    const float* fc_out_w    = (const float*)d_in[16];
    float* out = (float*)d_out;

    cudaFuncSetAttribute(gemm_nt_f16, cudaFuncAttributeMaxDynamicSharedMemorySize, GEMM_DSMEM);
    cudaFuncSetAttribute(gemm_nt_f16_n64, cudaFuncAttributeMaxDynamicSharedMemorySize, GEMM64_DSMEM);

    float *x;
    __half *xh, *qh, *kh, *vh, *kh6, *vh6, *att, *yh, *ff, *dech, *fvh;
    __half *wsi, *wso, *wcq, *wckv, *wco, *wl1, *wl2, *wfc;
    float *bckv;
    cudaGetSymbolAddress((void**)&x,    g_x);
    cudaGetSymbolAddress((void**)&xh,   g_xh);
    cudaGetSymbolAddress((void**)&qh,   g_qh);
    cudaGetSymbolAddress((void**)&kh,   g_kh);
    cudaGetSymbolAddress((void**)&vh,   g_vh);
    cudaGetSymbolAddress((void**)&kh6,  g_kh6);
    cudaGetSymbolAddress((void**)&vh6,  g_vh6);
    cudaGetSymbolAddress((void**)&att,  g_att);
    cudaGetSymbolAddress((void**)&yh,   g_yh);
    cudaGetSymbolAddress((void**)&ff,   g_ff);
    cudaGetSymbolAddress((void**)&dech, g_dech);
    cudaGetSymbolAddress((void**)&fvh,  g_fvh);
    cudaGetSymbolAddress((void**)&wsi,  g_w_selfin);
    cudaGetSymbolAddress((void**)&wso,  g_w_selfout);
    cudaGetSymbolAddress((void**)&wcq,  g_w_cq);
    cudaGetSymbolAddress((void**)&wckv, g_w_ckv);
    cudaGetSymbolAddress((void**)&wco,  g_w_crossout);
    cudaGetSymbolAddress((void**)&wl1,  g_w_lin1);
    cudaGetSymbolAddress((void**)&wl2,  g_w_lin2);
    cudaGetSymbolAddress((void**)&wfc,  g_w_fc);
    cudaGetSymbolAddress((void**)&bckv, g_b_ckv);

    // single mega-cvt for all plain fp32->fp16 conversions
    {
        CvtSegs cs;
        cs.src[0] = (const float4*)self_in_w;   cs.dst[0] = (uint2*)wsi; cs.n4[0] = NL*3*DD*DD/4;
        cs.src[1] = (const float4*)self_out_w;  cs.dst[1] = (uint2*)wso; cs.n4[1] = NL*DD*DD/4;
        cs.src[2] = (const float4*)cross_out_w; cs.dst[2] = (uint2*)wco; cs.n4[2] = NL*DD*DD/4;
        cs.src[3] = (const float4*)lin1_w;      cs.dst[3] = (uint2*)wl1; cs.n4[3] = NL*FFD*DD/4;
        cs.src[4] = (const float4*)lin2_w;      cs.dst[4] = (uint2*)wl2; cs.n4[4] = NL*DD*FFD/4;
        cs.src[5] = (const float4*)fc_out_w;    cs.dst[5] = (uint2*)wfc; cs.n4[5] = VOC*DD/4;
        cs.src[6] = (const float4*)fv;          cs.dst[6] = (uint2*)fvh; cs.n4[6] = MKV*DD/4;
        cvt_mega_kernel<<<2960, 256>>>(cs);
    }
    {
        int n4 = NL*3*DD*(DD/4);
        int blocks = (n4 + 255)/256;
        if (blocks > 8192) blocks = 8192;
        cvt_split_crossin_kernel<<<blocks, 256>>>((const float4*)cross_in_w, (uint2*)wcq, (uint2*)wckv);
    }
    gather_ckv_bias_kernel<<<(NL*2*DD + 255)/256, 256>>>(cross_in_b);

    add_pe_kernel<<<(MQ*DD + 255)/256, 256>>>(te);

    // hoisted: ALL layers' cross K/V in one batched GEMM
    gemm_nt_f16<<<gemm_grid(MKV, NL*2*DD), 256, GEMM_DSMEM>>>(
        fvh, wckv, bckv, nullptr, nullptr, MKV, NL*2*DD, DD, 0, 3, nullptr, kh6, vh6);

    for (int l = 0; l < NL; l++) {
        const __half* siw = wsi + (size_t)l*3*DD*DD;
        const float*  sib = self_in_b   + (size_t)l*3*DD;
        const __half* sow = wso + (size_t)l*DD*DD;
        const float*  sob = self_out_b  + (size_t)l*DD;
        const __half* cqw = wcq + (size_t)l*DD*DD;
        const float*  cib = cross_in_b  + (size_t)l*3*DD;
        const __half* cow = wco + (size_t)l*DD*DD;
        const float*  cob = cross_out_b + (size_t)l*DD;
        const __half* l1w = wl1 + (size_t)l*FFD*DD;
        const float*  l1b = lin1_b + (size_t)l*FFD;
        const __half* l2w = wl2 + (size_t)l*DD*FFD;
        const float*  l2b = lin2_b + (size_t)l*DD;

        // ---- self attention ----
        gemm_nt_f16<<<gemm_grid(MQ, 3*DD), 256, GEMM_DSMEM>>>(xh, siw, sib, nullptr, nullptr, MQ, 3*DD, DD, 0, 1, qh, kh, vh);
        flash_attn<<<dim3(SS/128, BHH), 256>>>(qh, kh, vh, att, SS, 1);
        gemm_nt_f16_n64<<<gemm64_grid(MQ, DD), 256, GEMM64_DSMEM>>>(att, sow, sob, yh, MQ, DD, DD, 0, nullptr);
        add_ln_kernel<<<MQ, 256>>>(yh, ln_w + (size_t)(l*3 + 0)*DD, ln_b + (size_t)(l*3 + 0)*DD);

        // ---- cross attention (K/V precomputed) ----
        gemm_nt_f16_n64<<<gemm64_grid(MQ, DD), 256, GEMM64_DSMEM>>>(xh, cqw, cib, nullptr, MQ, DD, DD, 2, qh);
        flash_attn<<<dim3(SS/128, BHH), 256>>>(qh, kh6 + (size_t)l*KVSZ, vh6 + (size_t)l*KVSZ, att, NVV, 0);
        gemm_nt_f16_n64<<<gemm64_grid(MQ, DD), 256, GEMM64_DSMEM>>>(att, cow, cob, yh, MQ, DD, DD, 0, nullptr);
        add_ln_kernel<<<MQ, 256>>>(yh, ln_w + (size_t)(l*3 + 1)*DD, ln_b + (size_t)(l*3 + 1)*DD);

        // ---- FFN ----
        gemm_nt_f16<<<gemm_grid(MQ, FFD), 256, GEMM_DSMEM>>>(xh, l1w, l1b, nullptr, ff, MQ, FFD, DD, 1, 0, nullptr, nullptr, nullptr);
        gemm_nt_f16_n64<<<gemm64_grid(MQ, DD), 256, GEMM64_DSMEM>>>(ff, l2w, l2b, yh, MQ, DD, FFD, 0, nullptr);
        add_ln_kernel<<<MQ, 256>>>(yh, ln_w + (size_t)(l*3 + 2)*DD, ln_b + (size_t)(l*3 + 2)*DD);
    }

    // ---- outputs: F_t prep + logits GEMM ----
    dec_softmax_kernel<<<MDEC, 256>>>(out + (size_t)MDEC*VOC);
    gemm_nt_f16<<<gemm_grid(MDEC, VOC), 256, GEMM_DSMEM>>>(dech, wfc, nullptr, out, nullptr, MDEC, VOC, DD, 0, 0, nullptr, nullptr, nullptr);
}

// round 17
// speedup vs baseline: 1.0541x; 1.0541x over previous
#include <cuda_runtime.h>
#include <cuda_fp16.h>
#include <math.h>
#include <stdint.h>

// ---------------- problem constants ----------------
#define BB   16
#define SS   256
#define NVV  196
#define DD   768
#define FFD  2048
#define VOC  30522
#define NL   6
#define NHH  8
#define HDIM 96
#define MQ   (BB*SS)          // 4096
#define MKV  (BB*NVV)         // 3136
#define BHH  (BB*NHH)         // 128
#define MDEC (BB*(SS-1))      // 4080
#define KVSZ (BHH*NVV*HDIM)

// ---------------- scratch (static device memory; no allocations) ----------------
__device__ float  g_x  [MQ*DD];
__device__ __half g_xh [MQ*DD];
__device__ __half g_qh [BHH*SS*HDIM];
__device__ __half g_kh [BHH*SS*HDIM];
__device__ __half g_vh [BHH*SS*HDIM];
__device__ __half g_kh6[NL*KVSZ];
__device__ __half g_vh6[NL*KVSZ];
__device__ __half g_att[MQ*DD];
__device__ __half g_yh [MQ*DD];
__device__ __half g_ff [MQ*FFD];
__device__ __half g_dech[MDEC*DD];
__device__ __half g_fvh[MKV*DD];

__device__ __half g_w_selfin [NL*3*DD*DD];
__device__ __half g_w_selfout[NL*DD*DD];
__device__ __half g_w_cq     [NL*DD*DD];
__device__ __half g_w_ckv    [NL*2*DD*DD];
__device__ __half g_w_crossout[NL*DD*DD];
__device__ __half g_w_lin1   [NL*FFD*DD];
__device__ __half g_w_lin2   [NL*DD*FFD];
__device__ __half g_w_fc     [VOC*DD];
__device__ float  g_b_ckv    [NL*2*DD];

// ---------------- reductions ----------------
__device__ __forceinline__ float blk_sum256(float v) {
    __shared__ float sh[8];
    #pragma unroll
    for (int o = 16; o > 0; o >>= 1) v += __shfl_xor_sync(0xffffffffu, v, o);
    __syncthreads();
    if ((threadIdx.x & 31) == 0) sh[threadIdx.x >> 5] = v;
    __syncthreads();
    float r = sh[0];
    #pragma unroll
    for (int i = 1; i < 8; i++) r += sh[i];
    return r;
}

__device__ __forceinline__ float blk_max256(float v) {
    __shared__ float sh[8];
    #pragma unroll
    for (int o = 16; o > 0; o >>= 1) v = fmaxf(v, __shfl_xor_sync(0xffffffffu, v, o));
    __syncthreads();
    if ((threadIdx.x & 31) == 0) sh[threadIdx.x >> 5] = v;
    __syncthreads();
    float r = sh[0];
    #pragma unroll
    for (int i = 1; i < 8; i++) r = fmaxf(r, sh[i]);
    return r;
}

// ---------------- mma helpers ----------------
__device__ __forceinline__ void mma_f16(float (&d)[4], const unsigned (&a)[4], const unsigned (&b)[2]) {
    asm volatile(
        "mma.sync.aligned.m16n8k16.row.col.f32.f16.f16.f32 "
        "{%0,%1,%2,%3}, {%4,%5,%6,%7}, {%8,%9}, {%0,%1,%2,%3};\n"
        : "+f"(d[0]), "+f"(d[1]), "+f"(d[2]), "+f"(d[3])
        : "r"(a[0]), "r"(a[1]), "r"(a[2]), "r"(a[3]), "r"(b[0]), "r"(b[1]));
}

__device__ __forceinline__ void ldsm4(unsigned &d0, unsigned &d1, unsigned &d2, unsigned &d3, uint32_t a) {
    asm volatile("ldmatrix.sync.aligned.m8n8.x4.shared.b16 {%0,%1,%2,%3}, [%4];"
                 : "=r"(d0), "=r"(d1), "=r"(d2), "=r"(d3) : "r"(a));
}

__device__ __forceinline__ uint32_t smem_u32(const void* p) {
    uint32_t a;
    asm("{ .reg .u64 t; cvta.to.shared.u64 t, %1; cvt.u32.u64 %0, t; }" : "=r"(a) : "l"(p));
    return a;
}

__device__ __forceinline__ void cp16(uint32_t dst, const void* src, bool pred) {
    int sz = pred ? 16 : 0;
    asm volatile("cp.async.cg.shared.global [%0], [%1], 16, %2;" :: "r"(dst), "l"(src), "r"(sz));
}
#define CP_COMMIT() asm volatile("cp.async.commit_group;" ::: "memory")
#define CP_WAIT1()  asm volatile("cp.async.wait_group 1;" ::: "memory")

// ---------------- fp32 -> fp16 conversion passes ----------------
#define NSEG 7
struct CvtSegs {
    const float4* src[NSEG];
    uint2*        dst[NSEG];
    int           n4[NSEG];
};

__global__ void cvt_mega_kernel(CvtSegs segs) {
    int tid0 = blockIdx.x*blockDim.x + threadIdx.x;
    int stride = gridDim.x*blockDim.x;
    #pragma unroll
    for (int s = 0; s < NSEG; s++) {
        const float4* in = segs.src[s];
        uint2* out = segs.dst[s];
        int n4 = segs.n4[s];
        for (int i = tid0; i < n4; i += stride) {
            float4 v = in[i];
            __half2 h0 = __floats2half2_rn(v.x, v.y);
            __half2 h1 = __floats2half2_rn(v.z, v.w);
            out[i] = make_uint2(*(uint32_t*)&h0, *(uint32_t*)&h1);
        }
    }
}

// fused: split cross_in_w [L,3*DD,DD] into per-layer Q [L,DD,DD] and KV [L,2*DD,DD], fp16
__global__ void cvt_split_crossin_kernel(const float4* __restrict__ in,
                                         uint2* __restrict__ wcq, uint2* __restrict__ wckv) {
    const int PR = DD/4;
    const int n4 = NL*3*DD*PR;
    int i = blockIdx.x*blockDim.x + threadIdx.x;
    int stride = gridDim.x*blockDim.x;
    for (; i < n4; i += stride) {
        float4 v = in[i];
        __half2 h0 = __floats2half2_rn(v.x, v.y);
        __half2 h1 = __floats2half2_rn(v.z, v.w);
        uint2 hv = make_uint2(*(uint32_t*)&h0, *(uint32_t*)&h1);
        int row = i / PR, col = i - row*PR;
        int l = row / (3*DD), r = row - l*3*DD;
        if (r < DD) wcq [(size_t)l*DD*PR   + (size_t)r*PR        + col] = hv;
        else        wckv[(size_t)l*2*DD*PR + (size_t)(r - DD)*PR + col] = hv;
    }
}

__global__ void gather_ckv_bias_kernel(const float* __restrict__ cib) {
    int i = blockIdx.x*blockDim.x + threadIdx.x;
    if (i >= NL*2*DD) return;
    int l = i / (2*DD);
    int rem = i - l*2*DD;
    g_b_ckv[i] = cib[l*3*DD + DD + rem];
}

// ---------------- main dense GEMM (fp16 mma m16n8k16, cp.async 3-stage, 128x128, K-chunk 32) ----------------
#define SKH 40
#define STG_B (128*SKH*2*2)
#define GEMM_DSMEM (3*STG_B)

__global__ __launch_bounds__(256, 2) void gemm_nt_f16(
    const __half* __restrict__ A, const __half* __restrict__ Bm,
    const float* __restrict__ bias, float* __restrict__ C, __half* __restrict__ Ch,
    int M, int N, int K, int relu, int mode,
    __half* __restrict__ dq, __half* __restrict__ dk, __half* __restrict__ dv)
{
    extern __shared__ unsigned sm[];
    const uint32_t sb = smem_u32(sm);
    const int tid  = threadIdx.x;
    const int lane = tid & 31;
    const int wid  = tid >> 5;
    const int m0   = blockIdx.y * 128;
    const int n0   = blockIdx.x * 128;
    const int wm   = (wid & 3) * 32;
    const int wn   = (wid >> 2) * 64;
    const int g    = lane >> 2;
    const int t    = lane & 3;

    const uint32_t aoffB = (uint32_t)((((lane & 7) + ((lane >> 3) & 1)*8)*SKH + ((lane >> 4) & 1)*8) * 2);
    const uint32_t boffB = (uint32_t)((((lane & 7) + ((lane >> 4) & 1)*8)*SKH + ((lane >> 3) & 1)*8) * 2);

    const int lrow = tid >> 1;
    const int segb = (tid & 1) * 2;

    float acc[2][8][4];
    #pragma unroll
    for (int mi = 0; mi < 2; mi++)
        #pragma unroll
        for (int ni = 0; ni < 8; ni++)
            #pragma unroll
            for (int e = 0; e < 4; e++) acc[mi][ni][e] = 0.f;

    const int NC = K >> 5;

    #pragma unroll
    for (int pc = 0; pc < 2; pc++) {
        const int k0 = pc << 5;
        const uint32_t sA = sb + (uint32_t)(pc * STG_B);
        const uint32_t sB = sA + (uint32_t)(128*SKH*2);
        #pragma unroll
        for (int e = 0; e < 2; e++) {
            int seg = segb + e;
            int gm = m0 + lrow;
            cp16(sA + (uint32_t)(lrow*SKH*2 + seg*16),
                 A + (size_t)(gm < M ? gm : 0)*K + k0 + seg*8, gm < M);
            int gn = n0 + lrow;
            cp16(sB + (uint32_t)(lrow*SKH*2 + seg*16),
                 Bm + (size_t)(gn < N ? gn : 0)*K + k0 + seg*8, gn < N);
        }
        CP_COMMIT();
    }

    for (int c = 0; c < NC; c++) {
        CP_WAIT1();
        __syncthreads();

        if (c + 2 < NC) {
            const int k0 = (c + 2) << 5;
            const int s = (c + 2) % 3;
            const uint32_t sA = sb + (uint32_t)(s * STG_B);
            const uint32_t sB = sA + (uint32_t)(128*SKH*2);
            #pragma unroll
            for (int e = 0; e < 2; e++) {
                int seg = segb + e;
                int gm = m0 + lrow;
                cp16(sA + (uint32_t)(lrow*SKH*2 + seg*16),
                     A + (size_t)(gm < M ? gm : 0)*K + k0 + seg*8, gm < M);
                int gn = n0 + lrow;
                cp16(sB + (uint32_t)(lrow*SKH*2 + seg*16),
                     Bm + (size_t)(gn < N ? gn : 0)*K + k0 + seg*8, gn < N);
            }
        }
        CP_COMMIT();

        const int s = c % 3;
        const uint32_t Acur = sb + (uint32_t)(s * STG_B);
        const uint32_t Bcur = Acur + (uint32_t)(128*SKH*2);
        #pragma unroll
        for (int ks = 0; ks < 2; ks++) {
            unsigned a[2][4], b[8][2];
            #pragma unroll
            for (int mi = 0; mi < 2; mi++)
                ldsm4(a[mi][0], a[mi][1], a[mi][2], a[mi][3],
                      Acur + (uint32_t)(((wm + mi*16)*SKH + ks*16)*2) + aoffB);
            #pragma unroll
            for (int nj = 0; nj < 4; nj++)
                ldsm4(b[2*nj][0], b[2*nj][1], b[2*nj+1][0], b[2*nj+1][1],
                      Bcur + (uint32_t)(((wn + nj*16)*SKH + ks*16)*2) + boffB);
            #pragma unroll
            for (int mi = 0; mi < 2; mi++)
                #pragma unroll
                for (int ni = 0; ni < 8; ni++)
                    mma_f16(acc[mi][ni], a[mi], b[ni]);
        }
    }

    // ---- epilogue ----
    #pragma unroll
    for (int mi = 0; mi < 2; mi++) {
        #pragma unroll
        for (int half_ = 0; half_ < 2; half_++) {
            int r = m0 + wm + mi*16 + g + half_*8;
            if (r >= M) continue;
            #pragma unroll
            for (int ni = 0; ni < 8; ni++) {
                int cn = n0 + wn + ni*8 + 2*t;
                if (cn >= N) continue;
                float v0 = acc[mi][ni][half_*2 + 0];
                float v1 = acc[mi][ni][half_*2 + 1];
                if (bias) { v0 += bias[cn]; if (cn+1 < N) v1 += bias[cn+1]; }
                if (mode == 0) {
                    if (relu) { v0 = fmaxf(v0, 0.f); v1 = fmaxf(v1, 0.f); }
                    if (Ch) {
                        __half2 hv = __floats2half2_rn(v0, v1);
                        if (cn + 1 < N) *(__half2*)(Ch + (size_t)r*N + cn) = hv;
                        else            Ch[(size_t)r*N + cn] = __float2half(v0);
                    } else {
                        if (cn + 1 < N) *(float2*)(C + (size_t)r*N + cn) = make_float2(v0, v1);
                        else            C[(size_t)r*N + cn] = v0;
                    }
                } else {
                    int bb_, s_, which, rem, hh, dd;
                    __half* base;
                    if (mode == 1) {         // self QKV
                        bb_ = r >> 8; s_ = r & 255;
                        which = cn / DD; rem = cn - which*DD;
                        hh = rem / HDIM; dd = rem - hh*HDIM;
                        base = (which == 0) ? dq : (which == 1) ? dk : dv;
                        base += (((size_t)((bb_<<3) + hh))*SS + s_)*HDIM + dd;
                    } else {                 // mode 3: batched cross KV
                        bb_ = r / NVV; s_ = r - bb_*NVV;
                        int l = cn / (2*DD);
                        rem = cn - l*2*DD;
                        which = rem / DD;
                        int rem2 = rem - which*DD;
                        hh = rem2 / HDIM; dd = rem2 - hh*HDIM;
                        base = ((which == 0) ? dk : dv) + (size_t)l*KVSZ;
                        base += (((size_t)((bb_<<3) + hh))*NVV + s_)*HDIM + dd;
                    }
                    *(__half2*)base = __floats2half2_rn(v0, v1);
                }
            }
        }
    }
}

// ---------------- small-N GEMM (128x64 tile, K-chunk 32) ----------------
#define STG64_B ((128+64)*SKH*2)
#define GEMM64_DSMEM (3*STG64_B)

__global__ __launch_bounds__(256, 2) void gemm_nt_f16_n64(
    const __half* __restrict__ A, const __half* __restrict__ Bm,
    const float* __restrict__ bias, __half* __restrict__ Ch,
    int M, int N, int K, int mode, __half* __restrict__ dq)
{
    extern __shared__ unsigned sm[];
    const uint32_t sb = smem_u32(sm);
    const int tid  = threadIdx.x;
    const int lane = tid & 31;
    const int wid  = tid >> 5;
    const int m0   = blockIdx.y * 128;
    const int n0   = blockIdx.x * 64;
    const int wm   = (wid & 3) * 32;
    const int wn   = (wid >> 2) * 32;
    const int g    = lane >> 2;
    const int t    = lane & 3;

    const uint32_t aoffB = (uint32_t)((((lane & 7) + ((lane >> 3) & 1)*8)*SKH + ((lane >> 4) & 1)*8) * 2);
    const uint32_t boffB = (uint32_t)((((lane & 7) + ((lane >> 4) & 1)*8)*SKH + ((lane >> 3) & 1)*8) * 2);

    const int larow = tid >> 1;
    const int lasegb = (tid & 1) * 2;
    const int lbrow = tid >> 2;
    const int lbseg = tid & 3;

    float acc[2][4][4];
    #pragma unroll
    for (int mi = 0; mi < 2; mi++)
        #pragma unroll
        for (int ni = 0; ni < 4; ni++)
            #pragma unroll
            for (int e = 0; e < 4; e++) acc[mi][ni][e] = 0.f;

    const int NC = K >> 5;

    #pragma unroll
    for (int pc = 0; pc < 2; pc++) {
        const int k0 = pc << 5;
        const uint32_t sA = sb + (uint32_t)(pc * STG64_B);
        const uint32_t sB = sA + (uint32_t)(128*SKH*2);
        #pragma unroll
        for (int e = 0; e < 2; e++) {
            int seg = lasegb + e;
            int gm = m0 + larow;
            cp16(sA + (uint32_t)(larow*SKH*2 + seg*16),
                 A + (size_t)(gm < M ? gm : 0)*K + k0 + seg*8, gm < M);
        }
        {
            int gn = n0 + lbrow;
            cp16(sB + (uint32_t)(lbrow*SKH*2 + lbseg*16),
                 Bm + (size_t)(gn < N ? gn : 0)*K + k0 + lbseg*8, gn < N);
        }
        CP_COMMIT();
    }

    for (int c = 0; c < NC; c++) {
        CP_WAIT1();
        __syncthreads();

        if (c + 2 < NC) {
            const int k0 = (c + 2) << 5;
            const int s = (c + 2) % 3;
            const uint32_t sA = sb + (uint32_t)(s * STG64_B);
            const uint32_t sB = sA + (uint32_t)(128*SKH*2);
            #pragma unroll
            for (int e = 0; e < 2; e++) {
                int seg = lasegb + e;
                int gm = m0 + larow;
                cp16(sA + (uint32_t)(larow*SKH*2 + seg*16),
                     A + (size_t)(gm < M ? gm : 0)*K + k0 + seg*8, gm < M);
            }
            {
                int gn = n0 + lbrow;
                cp16(sB + (uint32_t)(lbrow*SKH*2 + lbseg*16),
                     Bm + (size_t)(gn < N ? gn : 0)*K + k0 + lbseg*8, gn < N);
            }
        }
        CP_COMMIT();

        const int s = c % 3;
        const uint32_t Acur = sb + (uint32_t)(s * STG64_B);
        const uint32_t Bcur = Acur + (uint32_t)(128*SKH*2);
        #pragma unroll
        for (int ks = 0; ks < 2; ks++) {
            unsigned a[2][4], b[4][2];
            #pragma unroll
            for (int mi = 0; mi < 2; mi++)
                ldsm4(a[mi][0], a[mi][1], a[mi][2], a[mi][3],
                      Acur + (uint32_t)(((wm + mi*16)*SKH + ks*16)*2) + aoffB);
            #pragma unroll
            for (int nj = 0; nj < 2; nj++)
                ldsm4(b[2*nj][0], b[2*nj][1], b[2*nj+1][0], b[2*nj+1][1],
                      Bcur + (uint32_t)(((wn + nj*16)*SKH + ks*16)*2) + boffB);
            #pragma unroll
            for (int mi = 0; mi < 2; mi++)
                #pragma unroll
                for (int ni = 0; ni < 4; ni++)
                    mma_f16(acc[mi][ni], a[mi], b[ni]);
        }
    }

    #pragma unroll
    for (int mi = 0; mi < 2; mi++) {
        #pragma unroll
        for (int half_ = 0; half_ < 2; half_++) {
            int r = m0 + wm + mi*16 + g + half_*8;
            if (r >= M) continue;
            #pragma unroll
            for (int ni = 0; ni < 4; ni++) {
                int cn = n0 + wn + ni*8 + 2*t;
                if (cn >= N) continue;
                float v0 = acc[mi][ni][half_*2 + 0];
                float v1 = acc[mi][ni][half_*2 + 1];
                if (bias) { v0 += bias[cn]; if (cn+1 < N) v1 += bias[cn+1]; }
                if (mode == 0) {
                    __half2 hv = __floats2half2_rn(v0, v1);
                    if (cn + 1 < N) *(__half2*)(Ch + (size_t)r*N + cn) = hv;
                    else            Ch[(size_t)r*N + cn] = __float2half(v0);
                } else {
                    int bb_ = r >> 8, s_ = r & 255;
                    int hh = cn / HDIM, dd = cn - hh*HDIM;
                    __half* base = dq + (((size_t)((bb_<<3) + hh))*SS + s_)*HDIM + dd;
                    *(__half2*)base = __floats2half2_rn(v0, v1);
                }
            }
        }
    }
}

// ---------------- fused flash attention (fp16 mma m16n8k16) ----------------
#define FKS 104
#define FVS 40

__global__ __launch_bounds__(256) void flash_attn(
    const __half* __restrict__ Qh, const __half* __restrict__ Kh, const __half* __restrict__ Vh,
    __half* __restrict__ Oatt, int kvlen, int causal)
{
    __shared__ __half Ks[32*FKS];
    __shared__ __half Vs[96*FVS];
    __shared__ __half Ps[8][16*FVS];
    const int tid = threadIdx.x, w = tid >> 5, lane = tid & 31;
    const int g = lane >> 2, t = lane & 3;
    const int z = blockIdx.y;
    const int b = z >> 3, h = z & 7;
    const int q0 = blockIdx.x * 128;
    const float scale = 0.1020620726159658f;

    const __half* Qb = Qh + ((size_t)z*SS + q0)*HDIM;
    const __half* Kb = Kh + (size_t)z*kvlen*HDIM;
    const __half* Vb = Vh + (size_t)z*kvlen*HDIM;

    unsigned qa[6][4];
    {
        const __half* qr0 = Qb + (w*16 + g)*HDIM;
        const __half* qr1 = qr0 + 8*HDIM;
        #pragma unroll
        for (int ks = 0; ks < 6; ks++) {
            qa[ks][0] = *(const uint32_t*)(qr0 + ks*16 + 2*t);
            qa[ks][1] = *(const uint32_t*)(qr1 + ks*16 + 2*t);
            qa[ks][2] = *(const uint32_t*)(qr0 + ks*16 + 2*t + 8);
            qa[ks][3] = *(const uint32_t*)(qr1 + ks*16 + 2*t + 8);
        }
    }

    float oacc[12][4];
    #pragma unroll
    for (int n = 0; n < 12; n++) { oacc[n][0]=0.f; oacc[n][1]=0.f; oacc[n][2]=0.f; oacc[n][3]=0.f; }
    float m0 = -1e30f, m1 = -1e30f, l0 = 0.f, l1 = 0.f;
    const int row0 = q0 + w*16 + g;
    const int row1 = row0 + 8;

    const uint32_t KsA = smem_u32(Ks);
    const uint32_t VsA = smem_u32(Vs);
    const uint32_t PsA = smem_u32(Ps[w]);
    const uint32_t boffK = (uint32_t)((((lane & 7) + ((lane >> 4) & 1)*8)*FKS + ((lane >> 3) & 1)*8) * 2);
    const uint32_t boffV = (uint32_t)((((lane & 7) + ((lane >> 4) & 1)*8)*FVS + ((lane >> 3) & 1)*8) * 2);
    const uint32_t aoffP = (uint32_t)((((lane & 7) + ((lane >> 3) & 1)*8)*FVS + ((lane >> 4) & 1)*8) * 2);

    int ntiles = (kvlen + 31) >> 5;
    if (causal) { int lim = ((q0 + 127) >> 5) + 1; if (lim < ntiles) ntiles = lim; }

    for (int j = 0; j < ntiles; j++) {
        const int k0 = j*32;

        #pragma unroll
        for (int it = 0; it < 2; it++) {
            int idx = it*256 + tid;
            if (idx < 384) {
                int key = idx / 12, q8 = idx - key*12;
                uint4 v = make_uint4(0u,0u,0u,0u);
                if (k0 + key < kvlen) v = *(const uint4*)(Kb + (size_t)(k0+key)*HDIM + q8*8);
                *(uint4*)(Ks + key*FKS + q8*8) = v;
            }
        }
        #pragma unroll
        for (int it = 0; it < 3; it++) {
            int idx = it*256 + tid;
            int key = idx & 31, dq4 = idx >> 5;
            uint2 v = make_uint2(0u,0u);
            if (k0 + key < kvlen) v = *(const uint2*)(Vb + (size_t)(k0+key)*HDIM + dq4*4);
            __half2 p0 = *(__half2*)&v.x;
            __half2 p1 = *(__half2*)&v.y;
            Vs[(dq4*4+0)*FVS + key] = __low2half(p0);
            Vs[(dq4*4+1)*FVS + key] = __high2half(p0);
            Vs[(dq4*4+2)*FVS + key] = __low2half(p1);
            Vs[(dq4*4+3)*FVS + key] = __high2half(p1);
        }
        __syncthreads();

        const bool active = !(causal && k0 > q0 + w*16 + 15);
        if (active) {
            float sacc[4][4];
            #pragma unroll
            for (int n = 0; n < 4; n++) { sacc[n][0]=0.f; sacc[n][1]=0.f; sacc[n][2]=0.f; sacc[n][3]=0.f; }
            #pragma unroll
            for (int ks = 0; ks < 6; ks++) {
                unsigned bb[4][2];
                ldsm4(bb[0][0], bb[0][1], bb[1][0], bb[1][1],
                      KsA + (uint32_t)(ks*16*2) + boffK);
                ldsm4(bb[2][0], bb[2][1], bb[3][0], bb[3][1],
                      KsA + (uint32_t)((16*FKS + ks*16)*2) + boffK);
                #pragma unroll
                for (int n = 0; n < 4; n++) mma_f16(sacc[n], qa[ks], bb[n]);
            }
            #pragma unroll
            for (int n = 0; n < 4; n++) {
                sacc[n][0] *= scale; sacc[n][1] *= scale;
                sacc[n][2] *= scale; sacc[n][3] *= scale;
            }

            const bool need_mask = causal || (k0 + 31 >= kvlen);
            if (need_mask) {
                #pragma unroll
                for (int n = 0; n < 4; n++) {
                    int colb = k0 + n*8 + 2*t;
                    #pragma unroll
                    for (int e = 0; e < 4; e++) {
                        int col = colb + (e & 1);
                        int row = (e < 2) ? row0 : row1;
                        if (col >= kvlen || (causal && col > row)) sacc[n][e] = -1e9f;
                    }
                }
            }

            float tm0 = fmaxf(fmaxf(sacc[0][0], sacc[0][1]), fmaxf(sacc[1][0], sacc[1][1]));
            tm0 = fmaxf(tm0, fmaxf(fmaxf(sacc[2][0], sacc[2][1]), fmaxf(sacc[3][0], sacc[3][1])));
            float tm1 = fmaxf(fmaxf(sacc[0][2], sacc[0][3]), fmaxf(sacc[1][2], sacc[1][3]));
            tm1 = fmaxf(tm1, fmaxf(fmaxf(sacc[2][2], sacc[2][3]), fmaxf(sacc[3][2], sacc[3][3])));
            tm0 = fmaxf(tm0, __shfl_xor_sync(0xffffffffu, tm0, 1));
            tm0 = fmaxf(tm0, __shfl_xor_sync(0xffffffffu, tm0, 2));
            tm1 = fmaxf(tm1, __shfl_xor_sync(0xffffffffu, tm1, 1));
            tm1 = fmaxf(tm1, __shfl_xor_sync(0xffffffffu, tm1, 2));
            float mn0 = fmaxf(m0, tm0), mn1 = fmaxf(m1, tm1);
            float a0 = __expf(m0 - mn0), a1 = __expf(m1 - mn1);
            float rs0 = 0.f, rs1 = 0.f;
            #pragma unroll
            for (int n = 0; n < 4; n++) {
                sacc[n][0] = __expf(sacc[n][0] - mn0); rs0 += sacc[n][0];
                sacc[n][1] = __expf(sacc[n][1] - mn0); rs0 += sacc[n][1];
                sacc[n][2] = __expf(sacc[n][2] - mn1); rs1 += sacc[n][2];
                sacc[n][3] = __expf(sacc[n][3] - mn1); rs1 += sacc[n][3];
            }
            rs0 += __shfl_xor_sync(0xffffffffu, rs0, 1);
            rs0 += __shfl_xor_sync(0xffffffffu, rs0, 2);
            rs1 += __shfl_xor_sync(0xffffffffu, rs1, 1);
            rs1 += __shfl_xor_sync(0xffffffffu, rs1, 2);
            l0 = l0*a0 + rs0; l1 = l1*a1 + rs1;
            m0 = mn0; m1 = mn1;
            #pragma unroll
            for (int n = 0; n < 12; n++) {
                oacc[n][0] *= a0; oacc[n][1] *= a0;
                oacc[n][2] *= a1; oacc[n][3] *= a1;
            }

            #pragma unroll
            for (int n = 0; n < 4; n++) {
                *(__half2*)((char*)Ps[w] + ((g    )*FVS + n*8 + 2*t)*2) = __floats2half2_rn(sacc[n][0], sacc[n][1]);
                *(__half2*)((char*)Ps[w] + ((g + 8)*FVS + n*8 + 2*t)*2) = __floats2half2_rn(sacc[n][2], sacc[n][3]);
            }
            __syncwarp();

            #pragma unroll
            for (int ks = 0; ks < 2; ks++) {
                unsigned pa[4];
                ldsm4(pa[0], pa[1], pa[2], pa[3], PsA + (uint32_t)(ks*16*2) + aoffP);
                unsigned vb[12][2];
                #pragma unroll
                for (int nj = 0; nj < 6; nj++)
                    ldsm4(vb[2*nj][0], vb[2*nj][1], vb[2*nj+1][0], vb[2*nj+1][1],
                          VsA + (uint32_t)((nj*16*FVS + ks*16)*2) + boffV);
                #pragma unroll
                for (int n = 0; n < 12; n++) mma_f16(oacc[n], pa, vb[n]);
            }
        }
        __syncthreads();
    }

    float inv0 = 1.f / l0, inv1 = 1.f / l1;
    __half* o0 = Oatt + ((size_t)(b*SS + row0))*DD + h*HDIM;
    __half* o1 = o0 + (size_t)8*DD;
    #pragma unroll
    for (int n = 0; n < 12; n++) {
        int cc = n*8 + 2*t;
        *(__half2*)(o0 + cc) = __floats2half2_rn(oacc[n][0]*inv0, oacc[n][1]*inv0);
        *(__half2*)(o1 + cc) = __floats2half2_rn(oacc[n][2]*inv1, oacc[n][3]*inv1);
    }
}

// ---------------- elementwise / softmax / LN ----------------
__global__ void add_pe_kernel(const float* __restrict__ te) {
    int idx = blockIdx.x*blockDim.x + threadIdx.x;
    if (idx >= MQ*DD) return;
    int d = idx % DD;
    int s = (idx / DD) % SS;
    int i2 = d & ~1;
    const float kfac = 9.210340371976184f / (float)DD;
    float div = expf(-(float)i2 * kfac);
    float ang = (float)s * div;
    float pe = (d & 1) ? cosf(ang) : sinf(ang);
    float v = te[idx] + pe;
    g_x[idx] = v;
    g_xh[idx] = __float2half(v);
}

__global__ __launch_bounds__(256) void add_ln_kernel(const __half* __restrict__ y,
                                                     const float* __restrict__ w,
                                                     const float* __restrict__ b) {
    int r = blockIdx.x;
    int t = threadIdx.x;
    float vs[3];
    float s = 0.f;
    #pragma unroll
    for (int i = 0; i < 3; i++) {
        int c = t + i*256;
        vs[i] = g_x[(size_t)r*DD + c] + __half2float(y[(size_t)r*DD + c]);
        s += vs[i];
    }
    float mean = blk_sum256(s) * (1.f/DD);
    float ss = 0.f;
    #pragma unroll
    for (int i = 0; i < 3; i++) { float d0 = vs[i] - mean; ss += d0*d0; }
    float var = blk_sum256(ss) * (1.f/DD);
    float inv = rsqrtf(var + 1e-5f);
    #pragma unroll
    for (int i = 0; i < 3; i++) {
        int c = t + i*256;
        float o = (vs[i] - mean)*inv*w[c] + b[c];
        g_x[(size_t)r*DD + c] = o;
        g_xh[(size_t)r*DD + c] = __float2half(o);
    }
}

__global__ __launch_bounds__(256) void dec_softmax_kernel(float* __restrict__ outF) {
    int r = blockIdx.x;
    int t = threadIdx.x;
    int b = r / (SS-1);
    int s = r - b*(SS-1);
    const float* p = g_x + ((size_t)(b*SS + s))*DD;
    float vs[3]; float m = -3.0e38f;
    #pragma unroll
    for (int i = 0; i < 3; i++) { vs[i] = p[t + i*256]; m = fmaxf(m, vs[i]); }
    float mx = blk_max256(m);
    float s0 = 0.f;
    float ex[3];
    #pragma unroll
    for (int i = 0; i < 3; i++) { ex[i] = expf(vs[i] - mx); s0 += ex[i]; }
    float sum = blk_sum256(s0);
    #pragma unroll
    for (int i = 0; i < 3; i++) {
        int c = t + i*256;
        outF[(size_t)r*DD + c] = ex[i] / sum;
        g_dech[(size_t)r*DD + c] = __float2half(vs[i]);
    }
}

// ---------------- host orchestration ----------------
static inline dim3 gemm_grid(int M, int N) { return dim3((N + 127)/128, (M + 127)/128); }
static inline dim3 gemm64_grid(int M, int N) { return dim3((N + 63)/64, (M + 127)/128); }

extern "C" void kernel_launch(void* const* d_in, const int* in_sizes, int n_in,
                              void* d_out, int out_size) {
    (void)in_sizes; (void)n_in; (void)out_size;
    const float* fv          = (const float*)d_in[0];
    const float* te          = (const float*)d_in[1];
    const float* self_in_w   = (const float*)d_in[2];
    const float* self_in_b   = (const float*)d_in[3];
    const float* self_out_w  = (const float*)d_in[4];
    const float* self_out_b  = (const float*)d_in[5];
    const float* cross_in_w  = (const float*)d_in[6];
    const float* cross_in_b  = (const float*)d_in[7];
    const float* cross_out_w = (const float*)d_in[8];
    const float* cross_out_b = (const float*)d_in[9];
    const float* lin1_w      = (const float*)d_in[10];
    const float* lin1_b      = (const float*)d_in[11];
    const float* lin2_w      = (const float*)d_in[12];
    const float* lin2_b      = (const float*)d_in[13];
    const float* ln_w        = (const float*)d_in[14];
    const float* ln_b        = (const float*)d_in[15];
    const float* fc_out_w    = (const float*)d_in[16];
    float* out = (float*)d_out;

    cudaFuncSetAttribute(gemm_nt_f16, cudaFuncAttributeMaxDynamicSharedMemorySize, GEMM_DSMEM);
    cudaFuncSetAttribute(gemm_nt_f16_n64, cudaFuncAttributeMaxDynamicSharedMemorySize, GEMM64_DSMEM);

    float *x;
    __half *xh, *qh, *kh, *vh, *kh6, *vh6, *att, *yh, *ff, *dech, *fvh;
    __half *wsi, *wso, *wcq, *wckv, *wco, *wl1, *wl2, *wfc;
    float *bckv;
    cudaGetSymbolAddress((void**)&x,    g_x);
    cudaGetSymbolAddress((void**)&xh,   g_xh);
    cudaGetSymbolAddress((void**)&qh,   g_qh);
    cudaGetSymbolAddress((void**)&kh,   g_kh);
    cudaGetSymbolAddress((void**)&vh,   g_vh);
    cudaGetSymbolAddress((void**)&kh6,  g_kh6);
    cudaGetSymbolAddress((void**)&vh6,  g_vh6);
    cudaGetSymbolAddress((void**)&att,  g_att);
    cudaGetSymbolAddress((void**)&yh,   g_yh);
    cudaGetSymbolAddress((void**)&ff,   g_ff);
    cudaGetSymbolAddress((void**)&dech, g_dech);
    cudaGetSymbolAddress((void**)&fvh,  g_fvh);
    cudaGetSymbolAddress((void**)&wsi,  g_w_selfin);
    cudaGetSymbolAddress((void**)&wso,  g_w_selfout);
    cudaGetSymbolAddress((void**)&wcq,  g_w_cq);
    cudaGetSymbolAddress((void**)&wckv, g_w_ckv);
    cudaGetSymbolAddress((void**)&wco,  g_w_crossout);
    cudaGetSymbolAddress((void**)&wl1,  g_w_lin1);
    cudaGetSymbolAddress((void**)&wl2,  g_w_lin2);
    cudaGetSymbolAddress((void**)&wfc,  g_w_fc);
    cudaGetSymbolAddress((void**)&bckv, g_b_ckv);

    // single mega-cvt for all plain fp32->fp16 conversions
    {
        CvtSegs cs;
        cs.src[0] = (const float4*)self_in_w;   cs.dst[0] = (uint2*)wsi; cs.n4[0] = NL*3*DD*DD/4;
        cs.src[1] = (const float4*)self_out_w;  cs.dst[1] = (uint2*)wso; cs.n4[1] = NL*DD*DD/4;
        cs.src[2] = (const float4*)cross_out_w; cs.dst[2] = (uint2*)wco; cs.n4[2] = NL*DD*DD/4;
        cs.src[3] = (const float4*)lin1_w;      cs.dst[3] = (uint2*)wl1; cs.n4[3] = NL*FFD*DD/4;
        cs.src[4] = (const float4*)lin2_w;      cs.dst[4] = (uint2*)wl2; cs.n4[4] = NL*DD*FFD/4;
        cs.src[5] = (const float4*)fc_out_w;    cs.dst[5] = (uint2*)wfc; cs.n4[5] = VOC*DD/4;
        cs.src[6] = (const float4*)fv;          cs.dst[6] = (uint2*)fvh; cs.n4[6] = MKV*DD/4;
        cvt_mega_kernel<<<2960, 256>>>(cs);
    }
    {
        int n4 = NL*3*DD*(DD/4);
        int blocks = (n4 + 255)/256;
        if (blocks > 8192) blocks = 8192;
        cvt_split_crossin_kernel<<<blocks, 256>>>((const float4*)cross_in_w, (uint2*)wcq, (uint2*)wckv);
    }
    gather_ckv_bias_kernel<<<(NL*2*DD + 255)/256, 256>>>(cross_in_b);

    add_pe_kernel<<<(MQ*DD + 255)/256, 256>>>(te);

    // hoisted: ALL layers' cross K/V in one batched GEMM
    gemm_nt_f16<<<gemm_grid(MKV, NL*2*DD), 256, GEMM_DSMEM>>>(
        fvh, wckv, bckv, nullptr, nullptr, MKV, NL*2*DD, DD, 0, 3, nullptr, kh6, vh6);

    for (int l = 0; l < NL; l++) {
        const __half* siw = wsi + (size_t)l*3*DD*DD;
        const float*  sib = self_in_b   + (size_t)l*3*DD;
        const __half* sow = wso + (size_t)l*DD*DD;
        const float*  sob = self_out_b  + (size_t)l*DD;
        const __half* cqw = wcq + (size_t)l*DD*DD;
        const float*  cib = cross_in_b  + (size_t)l*3*DD;
        const __half* cow = wco + (size_t)l*DD*DD;
        const float*  cob = cross_out_b + (size_t)l*DD;
        const __half* l1w = wl1 + (size_t)l*FFD*DD;
        const float*  l1b = lin1_b + (size_t)l*FFD;
        const __half* l2w = wl2 + (size_t)l*DD*FFD;
        const float*  l2b = lin2_b + (size_t)l*DD;

        // ---- self attention ----
        gemm_nt_f16<<<gemm_grid(MQ, 3*DD), 256, GEMM_DSMEM>>>(xh, siw, sib, nullptr, nullptr, MQ, 3*DD, DD, 0, 1, qh, kh, vh);
        flash_attn<<<dim3(SS/128, BHH), 256>>>(qh, kh, vh, att, SS, 1);
        gemm_nt_f16_n64<<<gemm64_grid(MQ, DD), 256, GEMM64_DSMEM>>>(att, sow, sob, yh, MQ, DD, DD, 0, nullptr);
        add_ln_kernel<<<MQ, 256>>>(yh, ln_w + (size_t)(l*3 + 0)*DD, ln_b + (size_t)(l*3 + 0)*DD);

        // ---- cross attention (K/V precomputed) ----
        gemm_nt_f16_n64<<<gemm64_grid(MQ, DD), 256, GEMM64_DSMEM>>>(xh, cqw, cib, nullptr, MQ, DD, DD, 2, qh);
        flash_attn<<<dim3(SS/128, BHH), 256>>>(qh, kh6 + (size_t)l*KVSZ, vh6 + (size_t)l*KVSZ, att, NVV, 0);
        gemm_nt_f16_n64<<<gemm64_grid(MQ, DD), 256, GEMM64_DSMEM>>>(att, cow, cob, yh, MQ, DD, DD, 0, nullptr);
        add_ln_kernel<<<MQ, 256>>>(yh, ln_w + (size_t)(l*3 + 1)*DD, ln_b + (size_t)(l*3 + 1)*DD);

        // ---- FFN ----
        gemm_nt_f16<<<gemm_grid(MQ, FFD), 256, GEMM_DSMEM>>>(xh, l1w, l1b, nullptr, ff, MQ, FFD, DD, 1, 0, nullptr, nullptr, nullptr);
        gemm_nt_f16_n64<<<gemm64_grid(MQ, DD), 256, GEMM64_DSMEM>>>(ff, l2w, l2b, yh, MQ, DD, FFD, 0, nullptr);
        add_ln_kernel<<<MQ, 256>>>(yh, ln_w + (size_t)(l*3 + 2)*DD, ln_b + (size_t)(l*3 + 2)*DD);
    }

    // ---- outputs: F_t prep + logits GEMM ----
    dec_softmax_kernel<<<MDEC, 256>>>(out + (size_t)MDEC*VOC);
    gemm_nt_f16<<<gemm_grid(MDEC, VOC), 256, GEMM_DSMEM>>>(dech, wfc, nullptr, out, nullptr, MDEC, VOC, DD, 0, 0, nullptr, nullptr, nullptr);
}